// round 4
// baseline (speedup 1.0000x reference)
#include <cuda_runtime.h>
#include <math.h>

// Problem constants
#define NB    8
#define CC_   192
#define HH    112
#define WW    112
#define HW    (HH * WW)          // 12544
#define TILE  16
#define HALO  18
#define POS   (HALO * HALO)      // 324
#define FPOS  (17 * HALO)        // 306: rows 0..16 need forward dots
#define CCH   32                 // channels per block (one chunk)
#define NSPLIT (CC_ / CCH)       // 6 channel-split blocks per tile
#define INV_T 10.0f
#define NTILES (7 * 7 * NB)      // 392
#define TOTAL_TERMS (8.0 * 8.0 * 112.0 * 112.0)

// scratch layout per (tile, split): [ssq 324][fdE 306][fdS 306][fdSE 306][fdSW 306]
#define OFF_SSQ 0
#define OFF_E   324
#define OFF_S   630
#define OFF_SE  936
#define OFF_SW  1242
#define SCR     1548

__device__ float    g_scr[NTILES * NSPLIT * SCR];   // ~14.6 MB, each slice fully overwritten
__device__ unsigned g_tile_cnt[NTILES];             // zero-init; reset by epilogue block
__device__ double   g_acc = 0.0;
__device__ unsigned g_cnt = 0u;

__global__ __launch_bounds__(256, 5)
void dcl_kernel(const float* __restrict__ feat,
                const int*   __restrict__ labels,
                const int*   __restrict__ dirs,
                float*       __restrict__ out)
{
    __shared__ float s[CCH * POS];   // 41472 B; reused as reduction buffer in epilogue
    __shared__ float warpsum[8];
    __shared__ int   s_last;

    const int z     = blockIdx.z;
    const int n     = z / NSPLIT;        // batch index
    const int split = z - n * NSPLIT;    // channel chunk index
    const int ti  = blockIdx.y * TILE;
    const int tj  = blockIdx.x * TILE;
    const int tile_id = (n * 7 + blockIdx.y) * 7 + blockIdx.x;
    const int tid = threadIdx.x;

    // ---- per-thread fixed position slots ----
    const int p1   = tid;                 // always < 306
    const int r1   = p1 / HALO;
    const int c1   = p1 - r1 * HALO;
    const int ii1  = ti - 1 + r1;
    const int jj1  = tj - 1 + c1;
    const bool ok1 = (ii1 >= 0) & (ii1 < HH) & (jj1 >= 0) & (jj1 < WW);
    const int go1  = ok1 ? (ii1 * WW + jj1) : 0;
    const bool eok1 = (c1 < 17);

    const int p2   = tid + 256;
    const bool has2 = (p2 < POS);         // tid < 68
    const bool fd2  = (p2 < FPOS);        // tid < 50
    const int r2   = p2 / HALO;
    const int c2   = p2 - r2 * HALO;
    const int ii2  = ti - 1 + r2;
    const int jj2  = tj - 1 + c2;
    const bool ok2 = has2 & (ii2 >= 0) & (ii2 < HH) & (jj2 >= 0) & (jj2 < WW);
    const int go2  = ok2 ? (ii2 * WW + jj2) : 0;
    const bool eok2 = (c2 < 17);

    // ---- load this block's 32-channel chunk ----
    const float* fp = feat + ((size_t)n * CC_ + split * CCH) * HW;
#pragma unroll 8
    for (int c = 0; c < CCH; c++) {
        float v1 = 0.f;
        if (ok1) v1 = __ldg(fp + c * HW + go1);
        s[c * POS + p1] = v1;
        if (has2) {
            float v2 = 0.f;
            if (ok2) v2 = __ldg(fp + c * HW + go2);
            s[c * POS + p2] = v2;
        }
    }
    __syncthreads();

    // ---- partial sumsq + 4 forward dots over this chunk ----
    float ss1 = 0.f, fdE1 = 0.f, fdS1 = 0.f, fdSE1 = 0.f, fdSW1 = 0.f;
    float ss2 = 0.f, fdE2 = 0.f, fdS2 = 0.f, fdSE2 = 0.f, fdSW2 = 0.f;
#pragma unroll 8
    for (int c = 0; c < CCH; c++) {
        const float* sc = s + c * POS;
        {
            const float x = sc[p1];
            ss1 = fmaf(x, x, ss1);
            float vE  = eok1 ? sc[p1 + 1]        : 0.f;
            float vS  =        sc[p1 + HALO];
            float vSE = eok1 ? sc[p1 + HALO + 1] : 0.f;
            float vSW =        sc[p1 + HALO - 1];
            fdE1  = fmaf(x, vE,  fdE1);
            fdS1  = fmaf(x, vS,  fdS1);
            fdSE1 = fmaf(x, vSE, fdSE1);
            fdSW1 = fmaf(x, vSW, fdSW1);
        }
        if (has2) {
            const float x = sc[p2];
            ss2 = fmaf(x, x, ss2);
            if (fd2) {
                float vE  = eok2 ? sc[p2 + 1]        : 0.f;
                float vS  =        sc[p2 + HALO];
                float vSE = eok2 ? sc[p2 + HALO + 1] : 0.f;
                float vSW =        sc[p2 + HALO - 1];
                fdE2  = fmaf(x, vE,  fdE2);
                fdS2  = fmaf(x, vS,  fdS2);
                fdSE2 = fmaf(x, vSE, fdSE2);
                fdSW2 = fmaf(x, vSW, fdSW2);
            }
        }
    }

    // ---- publish partials to this split's private scratch slice ----
    float* scr = g_scr + ((size_t)tile_id * NSPLIT + split) * SCR;
    scr[OFF_SSQ + p1] = ss1;
    scr[OFF_E  + p1] = fdE1;  scr[OFF_S  + p1] = fdS1;
    scr[OFF_SE + p1] = fdSE1; scr[OFF_SW + p1] = fdSW1;
    if (has2) scr[OFF_SSQ + p2] = ss2;
    if (fd2) {
        scr[OFF_E  + p2] = fdE2;  scr[OFF_S  + p2] = fdS2;
        scr[OFF_SE + p2] = fdSE2; scr[OFF_SW + p2] = fdSW2;
    }

    // release: my stores -> fence -> counter
    __threadfence();
    __syncthreads();
    if (tid == 0) {
        const unsigned old = atomicAdd(&g_tile_cnt[tile_id], 1u);
        s_last = (old == NSPLIT - 1);
        if (s_last) g_tile_cnt[tile_id] = 0;   // safe: all 6 arrived; reset for next replay
    }
    __syncthreads();
    if (!s_last) return;
    __threadfence();   // acquire side

    // ---- epilogue block: reduce 6 slices into smem (reuse s) ----
    const float* tbase = g_scr + (size_t)tile_id * NSPLIT * SCR;
    for (int i = tid; i < SCR; i += 256) {
        float v = 0.f;
#pragma unroll
        for (int sp = 0; sp < NSPLIT; sp++) v += tbase[sp * SCR + i];
        s[i] = v;
    }
    __syncthreads();

    const float* ssq_sh  = s + OFF_SSQ;
    const float* fdE_sh  = s + OFF_E;
    const float* fdS_sh  = s + OFF_S;
    const float* fdSE_sh = s + OFF_SE;
    const float* fdSW_sh = s + OFF_SW;

    // ---- per-pixel loss over the 8 direction fields ----
    const int li = tid >> 4;
    const int lj = tid & 15;
    const int gi = ti + li;
    const int gj = tj + lj;
    const int p0 = (li + 1) * HALO + (lj + 1);

    const float ssc  = ssq_sh[p0];
    const float invp = (ssc >= 1e-24f) ? rsqrtf(ssc) : 1e12f;

    float logits[8];
    int   maskv[8];
    float esum = 0.f;

#pragma unroll
    for (int m = 0; m < 8; m++) {
        const int d0 = __ldg(&dirs[((size_t)m * 2 + 0) * HW + gi * WW + gj]);
        const int d1 = __ldg(&dirs[((size_t)m * 2 + 1) * HW + gi * WW + gj]);
        const int pn = p0 + d0 * HALO + d1;

        float draw;
        if (d0 == 0 && d1 == 0) {
            draw = ssc;                        // self dot == sumsq
        } else {
            const bool fwd = (d0 > 0) || (d0 == 0 && d1 > 0);
            const int  pq  = fwd ? p0 : pn;
            const int  a0  = fwd ? d0 : -d0;
            const int  a1  = fwd ? d1 : -d1;   // (0,1)(1,0)(1,1)(1,-1)
            const float* base = (a0 == 0) ? fdE_sh
                              : (a1 == 0) ? fdS_sh
                              : (a1 > 0)  ? fdSE_sh : fdSW_sh;
            draw = base[pq];
        }

        const float ssn  = ssq_sh[pn];
        const float invq = (ssn >= 1e-24f) ? rsqrtf(ssn) : 1e12f;
        const float logit = draw * invp * invq * INV_T;

        const int labm = __ldg(&labels[(size_t)m * HW + gi * WW + gj]);
        const int labg = __ldg(&labels[(size_t)n * HW + (gi + d0) * WW + (gj + d1)]);
        const int mk   = (labm == labg);

        logits[m] = logit;
        maskv[m]  = mk;
        esum += mk ? __expf(logit) : 0.f;
    }

    const float ld = __logf(esum + 1e-6f);
    float pix = 0.f;
#pragma unroll
    for (int m = 0; m < 8; m++)
        pix += maskv[m] ? (ld - logits[m]) : INFINITY;

    // ---- block reduction + grand-total protocol (R3-proven) ----
    float v = pix;
#pragma unroll
    for (int off = 16; off > 0; off >>= 1)
        v += __shfl_xor_sync(0xffffffffu, v, off);
    if ((tid & 31) == 0) warpsum[tid >> 5] = v;
    __syncthreads();

    if (tid == 0) {
        double bs = 0.0;
#pragma unroll
        for (int w = 0; w < 8; w++) bs += (double)warpsum[w];
        atomicAdd(&g_acc, bs);
        __threadfence();
        const unsigned done = atomicAdd(&g_cnt, 1u);
        if (done == NTILES - 1) {
            const double total = atomicAdd(&g_acc, 0.0);  // re-read: sees all adds
            out[0] = (float)(total / TOTAL_TERMS);
            g_acc = 0.0;
            g_cnt = 0u;
        }
    }
}

extern "C" void kernel_launch(void* const* d_in, const int* in_sizes, int n_in,
                              void* d_out, int out_size)
{
    const float* feat   = (const float*)d_in[0];
    const int*   labels = (const int*)  d_in[1];
    const int*   dirs   = (const int*)  d_in[2];
    float*       out    = (float*)d_out;

    dim3 grid(WW / TILE, HH / TILE, NB * NSPLIT);   // (7, 7, 48) = 2352 blocks
    dcl_kernel<<<grid, 256>>>(feat, labels, dirs, out);
}

// round 5
// speedup vs baseline: 2.5266x; 2.5266x over previous
#include <cuda_runtime.h>
#include <math.h>

#define NB    8
#define CC_   192
#define HH    112
#define WW    112
#define HW    (HH * WW)         // 12544
#define BAND  8                 // pixel rows per tile
#define NBAND (HH / BAND)       // 14
#define LR    10                // local rows incl. +/-1 halo
#define CPC   8                 // channels per smem chunk
#define NCHUNK 4                // chunks per block
#define SPLITS 6                // channel-split blocks per tile
#define CSPLIT (CPC * NCHUNK)   // 32 channels per block
#define NTILES (NB * NBAND)     // 112
#define INV_T 10.0f
#define TOTAL_TERMS (8.0 * 8.0 * 112.0 * 112.0)

// scratch slice layout (floats): ssq[10][112] fdE[8][112] fdS[9][112] fdSE[9][112] fdSW[9][112]
#define SSQ  0
#define FDE  1120
#define FDS  2016
#define FDSE 3024
#define FDSW 4032
#define SCR  5040

__device__ __align__(16) float g_scr[NTILES * SPLITS * SCR];  // ~13.5 MB
__device__ unsigned g_tile_cnt[NTILES];
__device__ double   g_acc = 0.0;
__device__ unsigned g_cnt = 0u;

__global__ __launch_bounds__(256, 5)
void dcl_kernel(const float* __restrict__ feat,
                const int*   __restrict__ labels,
                const int*   __restrict__ dirs,
                float*       __restrict__ out)
{
    __shared__ __align__(16) float s[CPC * LR * WW];  // 8960 floats = 35840 B
    __shared__ float warpsum[8];
    __shared__ int   s_last;

    const int band  = blockIdx.x;
    const int n     = blockIdx.y;
    const int split = blockIdx.z;
    const int tile  = n * NBAND + band;
    const int tid   = threadIdx.x;
    const int w     = tid >> 5;
    const int l     = tid & 31;

    // pixel-warp mapping (tid < 224): 4 consecutive pixels along j
    const int ri = tid / 28;            // 0..7 for tid<224
    const int jq = (tid % 28) * 4;      // 0..108
    // halo-warp mapping (warp 7)
    const int u   = tid - 224;
    const int hjq = ((u < 28 ? u : 27)) * 4;

    // accumulators (pixel warps: ssq/fdE/fdS/fdSE/fdSW at own pixel)
    // (halo warp reuse: a=ssq[row -1], e=ssq[row 8], s_/se/sw = fdS/fdSE/fdSW[row -1])
    float a0=0,a1=0,a2=0,a3=0;
    float e0=0,e1=0,e2=0,e3=0;
    float f0=0,f1=0,f2=0,f3=0;
    float g0=0,g1=0,g2=0,g3=0;
    float h0=0,h1=0,h2=0,h3=0;

    const float* fbase = feat + ((size_t)n * CC_ + split * CSPLIT) * HW;
    const unsigned sbase = (unsigned)__cvta_generic_to_shared(s);

    for (int ch = 0; ch < NCHUNK; ch++) {
        // ---- cp.async load: warp w owns rows w, w+8, ..., w+72 of 80 (c,r) rows ----
        if (l < 28) {
            int r = w, c = 0;
            const float* fp = fbase + (size_t)ch * CPC * HW;
#pragma unroll
            for (int k = 0; k < 10; k++) {
                const int  gi  = band * BAND - 1 + r;
                const bool inb = (gi >= 0) & (gi < HH);
                const float* src = fp + (size_t)c * HW + (inb ? gi : 0) * WW + l * 4;
                const unsigned dst = sbase + (unsigned)(((c * LR + r) * WW + l * 4) * 4);
                const int sz = inb ? 16 : 0;    // sz=0 -> zero-fill 16B (OOB halo rows)
                asm volatile("cp.async.cg.shared.global [%0], [%1], 16, %2;\n"
                             :: "r"(dst), "l"(src), "r"(sz));
                r += 8; if (r >= LR) { r -= LR; c++; }
            }
        }
        asm volatile("cp.async.commit_group;\n");
        asm volatile("cp.async.wait_group 0;\n");
        __syncthreads();

        // ---- compute partials for this 8-channel chunk ----
        if (tid < 224) {
            const float* base = s + (ri + 1) * WW + jq;
            const bool hasR = (jq < 108);
            const bool hasL = (jq > 0);
#pragma unroll
            for (int c = 0; c < CPC; c++) {
                const float* rA = base + c * (LR * WW);   // pixel row
                const float* rB = rA + WW;                // row below
                const float4 x = *(const float4*)rA;
                const float xR = hasR ? rA[4]  : 0.f;
                const float4 y = *(const float4*)rB;
                const float yL = hasL ? rB[-1] : 0.f;
                const float yR = hasR ? rB[4]  : 0.f;
                a0=fmaf(x.x,x.x,a0); a1=fmaf(x.y,x.y,a1); a2=fmaf(x.z,x.z,a2); a3=fmaf(x.w,x.w,a3);
                e0=fmaf(x.x,x.y,e0); e1=fmaf(x.y,x.z,e1); e2=fmaf(x.z,x.w,e2); e3=fmaf(x.w,xR ,e3);
                f0=fmaf(x.x,y.x,f0); f1=fmaf(x.y,y.y,f1); f2=fmaf(x.z,y.z,f2); f3=fmaf(x.w,y.w,f3);
                g0=fmaf(x.x,y.y,g0); g1=fmaf(x.y,y.z,g1); g2=fmaf(x.z,y.w,g2); g3=fmaf(x.w,yR ,g3);
                h0=fmaf(x.x,yL ,h0); h1=fmaf(x.y,y.x,h1); h2=fmaf(x.z,y.y,h2); h3=fmaf(x.w,y.z,h3);
            }
        } else {
            const float* base0 = s + hjq;                 // local row 0 (image row band*8-1)
            const bool hasR = (hjq < 108);
            const bool hasL = (hjq > 0);
#pragma unroll
            for (int c = 0; c < CPC; c++) {
                const float* rA = base0 + c * (LR * WW);  // row -1
                const float* rB = rA + WW;                // row 0
                const float* rT = rA + 9 * WW;            // row 8
                const float4 x = *(const float4*)rA;
                const float4 y = *(const float4*)rB;
                const float yL = hasL ? rB[-1] : 0.f;
                const float yR = hasR ? rB[4]  : 0.f;
                const float4 t = *(const float4*)rT;
                a0=fmaf(x.x,x.x,a0); a1=fmaf(x.y,x.y,a1); a2=fmaf(x.z,x.z,a2); a3=fmaf(x.w,x.w,a3);
                e0=fmaf(t.x,t.x,e0); e1=fmaf(t.y,t.y,e1); e2=fmaf(t.z,t.z,e2); e3=fmaf(t.w,t.w,e3);
                f0=fmaf(x.x,y.x,f0); f1=fmaf(x.y,y.y,f1); f2=fmaf(x.z,y.z,f2); f3=fmaf(x.w,y.w,f3);
                g0=fmaf(x.x,y.y,g0); g1=fmaf(x.y,y.z,g1); g2=fmaf(x.z,y.w,g2); g3=fmaf(x.w,yR ,g3);
                h0=fmaf(x.x,yL ,h0); h1=fmaf(x.y,y.x,h1); h2=fmaf(x.z,y.y,h2); h3=fmaf(x.w,y.z,h3);
            }
        }
        __syncthreads();  // compute done before next chunk's cp.async overwrites s
    }

    // ---- publish partials (float4 STG, private slice -> no atomics) ----
    float* scr = g_scr + ((size_t)tile * SPLITS + split) * SCR;
    if (tid < 224) {
        *(float4*)&scr[SSQ  + (ri + 1) * WW + jq] = make_float4(a0,a1,a2,a3);
        *(float4*)&scr[FDE  +  ri      * WW + jq] = make_float4(e0,e1,e2,e3);
        *(float4*)&scr[FDS  + (ri + 1) * WW + jq] = make_float4(f0,f1,f2,f3);
        *(float4*)&scr[FDSE + (ri + 1) * WW + jq] = make_float4(g0,g1,g2,g3);
        *(float4*)&scr[FDSW + (ri + 1) * WW + jq] = make_float4(h0,h1,h2,h3);
    } else if (u < 28) {
        *(float4*)&scr[SSQ  + 0 * WW + hjq] = make_float4(a0,a1,a2,a3);   // row -1 ssq
        *(float4*)&scr[SSQ  + 9 * WW + hjq] = make_float4(e0,e1,e2,e3);   // row 8 ssq
        *(float4*)&scr[FDS  + 0 * WW + hjq] = make_float4(f0,f1,f2,f3);
        *(float4*)&scr[FDSE + 0 * WW + hjq] = make_float4(g0,g1,g2,g3);
        *(float4*)&scr[FDSW + 0 * WW + hjq] = make_float4(h0,h1,h2,h3);
    }

    __threadfence();
    __syncthreads();
    if (tid == 0) {
        const unsigned old = atomicAdd(&g_tile_cnt[tile], 1u);
        s_last = (old == SPLITS - 1);
        if (s_last) g_tile_cnt[tile] = 0;  // all arrived; reset for next replay
    }
    __syncthreads();
    if (!s_last) return;
    __threadfence();

    // ---- epilogue: reduce 6 slices into smem ----
    const float* tb = g_scr + (size_t)tile * SPLITS * SCR;
    for (int i = tid; i < SCR; i += 256) {
        s[i] = tb[i] + tb[SCR + i] + tb[2 * SCR + i]
             + tb[3 * SCR + i] + tb[4 * SCR + i] + tb[5 * SCR + i];
    }
    __syncthreads();

    float pix = 0.f;
    if (tid < 224) {
        const float* ssq = s + SSQ;
        const int i0 = band * BAND + ri;
        const int lr = ri + 1;
#pragma unroll
        for (int k = 0; k < 4; k++) {
            const int j   = jq + k;
            const float ssc  = ssq[lr * WW + j];
            const float invp = (ssc >= 1e-24f) ? rsqrtf(ssc) : 1e12f;
            float logits[8]; int maskv[8]; float esum = 0.f;
#pragma unroll
            for (int m = 0; m < 8; m++) {
                const int d0 = __ldg(&dirs[((size_t)m * 2 + 0) * HW + i0 * WW + j]);
                const int d1 = __ldg(&dirs[((size_t)m * 2 + 1) * HW + i0 * WW + j]);
                float draw;
                if ((d0 | d1) == 0) {
                    draw = ssc;                        // self dot == sumsq
                } else {
                    const bool fwd = (d0 > 0) || (d0 == 0 && d1 > 0);
                    const int plr = fwd ? lr : lr + d0;
                    const int pj  = fwd ? j  : j  + d1;
                    const int A0  = fwd ? d0 : -d0;
                    const int A1  = fwd ? d1 : -d1;    // one of (0,1)(1,0)(1,1)(1,-1)
                    const float* base =
                        (A0 == 0) ? (s + FDE - WW)     // fdE indexed by pixel row = plr-1
                      : (A1 == 0) ? (s + FDS)
                      : (A1 > 0)  ? (s + FDSE) : (s + FDSW);
                    draw = base[plr * WW + pj];
                }
                const float ssn  = ssq[(lr + d0) * WW + (j + d1)];
                const float invq = (ssn >= 1e-24f) ? rsqrtf(ssn) : 1e12f;
                const float logit = draw * invp * invq * INV_T;
                const int labm = __ldg(&labels[(size_t)m * HW + i0 * WW + j]);
                const int labg = __ldg(&labels[(size_t)n * HW + (i0 + d0) * WW + (j + d1)]);
                const int mk   = (labm == labg);
                logits[m] = logit; maskv[m] = mk;
                esum += mk ? __expf(logit) : 0.f;
            }
            const float ld = __logf(esum + 1e-6f);
#pragma unroll
            for (int m = 0; m < 8; m++)
                pix += maskv[m] ? (ld - logits[m]) : INFINITY;
        }
    }

    // ---- block reduction + grand-total protocol (proven in R3/R4) ----
    float v = pix;
#pragma unroll
    for (int off = 16; off > 0; off >>= 1)
        v += __shfl_xor_sync(0xffffffffu, v, off);
    if ((tid & 31) == 0) warpsum[tid >> 5] = v;
    __syncthreads();
    if (tid == 0) {
        double bs = 0.0;
#pragma unroll
        for (int q = 0; q < 8; q++) bs += (double)warpsum[q];
        atomicAdd(&g_acc, bs);
        __threadfence();
        const unsigned done = atomicAdd(&g_cnt, 1u);
        if (done == NTILES - 1) {
            const double total = atomicAdd(&g_acc, 0.0);  // re-read: sees all adds
            out[0] = (float)(total / TOTAL_TERMS);
            g_acc = 0.0;
            g_cnt = 0u;
        }
    }
}

extern "C" void kernel_launch(void* const* d_in, const int* in_sizes, int n_in,
                              void* d_out, int out_size)
{
    const float* feat   = (const float*)d_in[0];
    const int*   labels = (const int*)  d_in[1];
    const int*   dirs   = (const int*)  d_in[2];
    float*       out    = (float*)d_out;

    dim3 grid(NBAND, NB, SPLITS);   // (14, 8, 6) = 672 blocks, single wave at 5/SM
    dcl_kernel<<<grid, 256>>>(feat, labels, dirs, out);
}

// round 6
// speedup vs baseline: 2.7956x; 1.1065x over previous
#include <cuda_runtime.h>
#include <math.h>

#define NB    8
#define CC_   192
#define HH    112
#define WW    112
#define HW    (HH * WW)         // 12544
#define BAND  8                 // pixel rows per tile
#define NBAND (HH / BAND)       // 14
#define LR    10                // local rows incl. +/-1 halo
#define CPC   4                 // channels per smem chunk
#define NCHUNK 8                // chunks per block (32 channels total)
#define SPLITS 6                // channel-split blocks per tile
#define CSPLIT (CPC * NCHUNK)   // 32 channels per block
#define NTILES (NB * NBAND)     // 112
#define CHF   (CPC * LR * WW)   // 4480 floats per buffer
#define INV_T 10.0f
#define TOTAL_TERMS (8.0 * 8.0 * 112.0 * 112.0)

// scratch slice layout (floats): ssq[10][112] fdE[8][112] fdS[9][112] fdSE[9][112] fdSW[9][112]
#define SSQ  0
#define FDE  1120
#define FDS  2016
#define FDSE 3024
#define FDSW 4032
#define SCR  5040               // 20160 B, 16B-aligned

__device__ __align__(16) float g_scr[NTILES * SPLITS * SCR];  // ~13.5 MB
__device__ unsigned g_tile_cnt[NTILES];
__device__ double   g_acc = 0.0;
__device__ unsigned g_cnt = 0u;

__global__ __launch_bounds__(256, 5)
void dcl_kernel(const float* __restrict__ feat,
                const int*   __restrict__ labels,
                const int*   __restrict__ dirs,
                float*       __restrict__ out)
{
    __shared__ __align__(16) float s[2 * CHF];   // 35840 B double buffer
    __shared__ float warpsum[8];
    __shared__ int   s_last;

    const int band  = blockIdx.x;
    const int n     = blockIdx.y;
    const int split = blockIdx.z;
    const int tile  = n * NBAND + band;
    const int tid   = threadIdx.x;
    const int w     = tid >> 5;
    const int l     = tid & 31;

    // pixel-warp mapping (tid < 224): 4 consecutive pixels along j
    const int ri = tid / 28;            // 0..7 for tid<224
    const int jq = (tid % 28) * 4;      // 0..108
    // halo-warp mapping (warp 7)
    const int u   = tid - 224;
    const int hjq = ((u < 28 ? u : 27)) * 4;

    float a0=0,a1=0,a2=0,a3=0;
    float e0=0,e1=0,e2=0,e3=0;
    float f0=0,f1=0,f2=0,f3=0;
    float g0=0,g1=0,g2=0,g3=0;
    float h0=0,h1=0,h2=0,h3=0;

    const float* fbase = feat + ((size_t)n * CC_ + split * CSPLIT) * HW;
    const unsigned sb0 = (unsigned)__cvta_generic_to_shared(s);

    // ---- cp.async issue of one 4-channel chunk into buffer buf ----
    // rows (c,r): 4*10 = 40; warp w handles idx = w, w+8, ..., w+32 (5 rows)
    auto issue_chunk = [&](int ch, int buf) {
        if (l < 28) {
            const float* fp = fbase + (size_t)ch * CPC * HW;
            const unsigned dbase = sb0 + (unsigned)buf * (CHF * 4);
            int r = w, c = 0;
#pragma unroll
            for (int k = 0; k < 5; k++) {
                const int  gi  = band * BAND - 1 + r;
                const bool inb = (gi >= 0) & (gi < HH);
                const float* src = fp + (size_t)c * HW + (inb ? gi : 0) * WW + l * 4;
                const unsigned dst = dbase + (unsigned)(((c * LR + r) * WW + l * 4) * 4);
                const int sz = inb ? 16 : 0;   // sz=0 -> zero-fill (OOB halo rows)
                asm volatile("cp.async.cg.shared.global [%0], [%1], 16, %2;\n"
                             :: "r"(dst), "l"(src), "r"(sz));
                r += 8; if (r >= LR) { r -= LR; c++; }
            }
        }
        asm volatile("cp.async.commit_group;\n");
    };

    // ---- prologue: two chunks in flight ----
    issue_chunk(0, 0);
    issue_chunk(1, 1);

    for (int ch = 0; ch < NCHUNK; ch++) {
        if (ch < NCHUNK - 1) asm volatile("cp.async.wait_group 1;\n");
        else                 asm volatile("cp.async.wait_group 0;\n");
        __syncthreads();   // chunk ch's buffer visible to all threads

        const float* sbuf = s + (ch & 1) * CHF;
        if (tid < 224) {
            const float* base = sbuf + (ri + 1) * WW + jq;
            const bool hasR = (jq < 108);
            const bool hasL = (jq > 0);
#pragma unroll
            for (int c = 0; c < CPC; c++) {
                const float* rA = base + c * (LR * WW);   // pixel row
                const float* rB = rA + WW;                // row below
                const float4 x = *(const float4*)rA;
                const float xR = hasR ? rA[4]  : 0.f;
                const float4 y = *(const float4*)rB;
                const float yL = hasL ? rB[-1] : 0.f;
                const float yR = hasR ? rB[4]  : 0.f;
                a0=fmaf(x.x,x.x,a0); a1=fmaf(x.y,x.y,a1); a2=fmaf(x.z,x.z,a2); a3=fmaf(x.w,x.w,a3);
                e0=fmaf(x.x,x.y,e0); e1=fmaf(x.y,x.z,e1); e2=fmaf(x.z,x.w,e2); e3=fmaf(x.w,xR ,e3);
                f0=fmaf(x.x,y.x,f0); f1=fmaf(x.y,y.y,f1); f2=fmaf(x.z,y.z,f2); f3=fmaf(x.w,y.w,f3);
                g0=fmaf(x.x,y.y,g0); g1=fmaf(x.y,y.z,g1); g2=fmaf(x.z,y.w,g2); g3=fmaf(x.w,yR ,g3);
                h0=fmaf(x.x,yL ,h0); h1=fmaf(x.y,y.x,h1); h2=fmaf(x.z,y.y,h2); h3=fmaf(x.w,y.z,h3);
            }
        } else {
            const float* base0 = sbuf + hjq;              // local row 0 (image row band*8-1)
            const bool hasR = (hjq < 108);
            const bool hasL = (hjq > 0);
#pragma unroll
            for (int c = 0; c < CPC; c++) {
                const float* rA = base0 + c * (LR * WW);  // row -1
                const float* rB = rA + WW;                // row 0
                const float* rT = rA + 9 * WW;            // row 8
                const float4 x = *(const float4*)rA;
                const float4 y = *(const float4*)rB;
                const float yL = hasL ? rB[-1] : 0.f;
                const float yR = hasR ? rB[4]  : 0.f;
                const float4 t = *(const float4*)rT;
                a0=fmaf(x.x,x.x,a0); a1=fmaf(x.y,x.y,a1); a2=fmaf(x.z,x.z,a2); a3=fmaf(x.w,x.w,a3);
                e0=fmaf(t.x,t.x,e0); e1=fmaf(t.y,t.y,e1); e2=fmaf(t.z,t.z,e2); e3=fmaf(t.w,t.w,e3);
                f0=fmaf(x.x,y.x,f0); f1=fmaf(x.y,y.y,f1); f2=fmaf(x.z,y.z,f2); f3=fmaf(x.w,y.w,f3);
                g0=fmaf(x.x,y.y,g0); g1=fmaf(x.y,y.z,g1); g2=fmaf(x.z,y.w,g2); g3=fmaf(x.w,yR ,g3);
                h0=fmaf(x.x,yL ,h0); h1=fmaf(x.y,y.x,h1); h2=fmaf(x.z,y.y,h2); h3=fmaf(x.w,y.z,h3);
            }
        }
        __syncthreads();   // all reads of this buffer done before refill
        if (ch + 2 < NCHUNK) issue_chunk(ch + 2, ch & 1);
    }

    // ---- publish partials (float4 STG, private slice -> no atomics) ----
    float* scr = g_scr + ((size_t)tile * SPLITS + split) * SCR;
    if (tid < 224) {
        *(float4*)&scr[SSQ  + (ri + 1) * WW + jq] = make_float4(a0,a1,a2,a3);
        *(float4*)&scr[FDE  +  ri      * WW + jq] = make_float4(e0,e1,e2,e3);
        *(float4*)&scr[FDS  + (ri + 1) * WW + jq] = make_float4(f0,f1,f2,f3);
        *(float4*)&scr[FDSE + (ri + 1) * WW + jq] = make_float4(g0,g1,g2,g3);
        *(float4*)&scr[FDSW + (ri + 1) * WW + jq] = make_float4(h0,h1,h2,h3);
    } else if (u < 28) {
        *(float4*)&scr[SSQ  + 0 * WW + hjq] = make_float4(a0,a1,a2,a3);   // row -1 ssq
        *(float4*)&scr[SSQ  + 9 * WW + hjq] = make_float4(e0,e1,e2,e3);   // row 8 ssq
        *(float4*)&scr[FDS  + 0 * WW + hjq] = make_float4(f0,f1,f2,f3);
        *(float4*)&scr[FDSE + 0 * WW + hjq] = make_float4(g0,g1,g2,g3);
        *(float4*)&scr[FDSW + 0 * WW + hjq] = make_float4(h0,h1,h2,h3);
    }

    __threadfence();
    __syncthreads();
    if (tid == 0) {
        const unsigned old = atomicAdd(&g_tile_cnt[tile], 1u);
        s_last = (old == SPLITS - 1);
        if (s_last) g_tile_cnt[tile] = 0;  // all arrived; reset for next replay
    }
    __syncthreads();
    if (!s_last) return;
    __threadfence();

    // ---- epilogue: reduce 6 slices into smem (float4) ----
    {
        const float4* tb4 = (const float4*)(g_scr + (size_t)tile * SPLITS * SCR);
        float4* s4 = (float4*)s;
        const int Q = SCR / 4;   // 1260
        for (int i = tid; i < Q; i += 256) {
            float4 v0 = tb4[i],         v1 = tb4[Q + i],     v2 = tb4[2 * Q + i];
            float4 v3 = tb4[3 * Q + i], v4 = tb4[4 * Q + i], v5 = tb4[5 * Q + i];
            float4 r;
            r.x = v0.x + v1.x + v2.x + v3.x + v4.x + v5.x;
            r.y = v0.y + v1.y + v2.y + v3.y + v4.y + v5.y;
            r.z = v0.z + v1.z + v2.z + v3.z + v4.z + v5.z;
            r.w = v0.w + v1.w + v2.w + v3.w + v4.w + v5.w;
            s4[i] = r;
        }
    }
    __syncthreads();

    float pix = 0.f;
    if (tid < 224) {
        const float* ssq = s + SSQ;
        const int i0 = band * BAND + ri;
        const int lr = ri + 1;
#pragma unroll
        for (int k = 0; k < 4; k++) {
            const int j   = jq + k;
            const float ssc  = ssq[lr * WW + j];
            const float invp = (ssc >= 1e-24f) ? rsqrtf(ssc) : 1e12f;
            float logits[8]; int maskv[8]; float esum = 0.f;
#pragma unroll
            for (int m = 0; m < 8; m++) {
                const int d0 = __ldg(&dirs[((size_t)m * 2 + 0) * HW + i0 * WW + j]);
                const int d1 = __ldg(&dirs[((size_t)m * 2 + 1) * HW + i0 * WW + j]);
                float draw;
                if ((d0 | d1) == 0) {
                    draw = ssc;                        // self dot == sumsq
                } else {
                    const bool fwd = (d0 > 0) || (d0 == 0 && d1 > 0);
                    const int plr = fwd ? lr : lr + d0;
                    const int pj  = fwd ? j  : j  + d1;
                    const int A0  = fwd ? d0 : -d0;
                    const int A1  = fwd ? d1 : -d1;    // one of (0,1)(1,0)(1,1)(1,-1)
                    const float* base =
                        (A0 == 0) ? (s + FDE - WW)     // fdE indexed by pixel row = plr-1
                      : (A1 == 0) ? (s + FDS)
                      : (A1 > 0)  ? (s + FDSE) : (s + FDSW);
                    draw = base[plr * WW + pj];
                }
                const float ssn  = ssq[(lr + d0) * WW + (j + d1)];
                const float invq = (ssn >= 1e-24f) ? rsqrtf(ssn) : 1e12f;
                const float logit = draw * invp * invq * INV_T;
                const int labm = __ldg(&labels[(size_t)m * HW + i0 * WW + j]);
                const int labg = __ldg(&labels[(size_t)n * HW + (i0 + d0) * WW + (j + d1)]);
                const int mk   = (labm == labg);
                logits[m] = logit; maskv[m] = mk;
                esum += mk ? __expf(logit) : 0.f;
            }
            const float ld = __logf(esum + 1e-6f);
#pragma unroll
            for (int m = 0; m < 8; m++)
                pix += maskv[m] ? (ld - logits[m]) : INFINITY;
        }
    }

    // ---- block reduction + grand-total protocol (proven R3-R5) ----
    float v = pix;
#pragma unroll
    for (int off = 16; off > 0; off >>= 1)
        v += __shfl_xor_sync(0xffffffffu, v, off);
    if ((tid & 31) == 0) warpsum[tid >> 5] = v;
    __syncthreads();
    if (tid == 0) {
        double bs = 0.0;
#pragma unroll
        for (int q = 0; q < 8; q++) bs += (double)warpsum[q];
        atomicAdd(&g_acc, bs);
        __threadfence();
        const unsigned done = atomicAdd(&g_cnt, 1u);
        if (done == NTILES - 1) {
            const double total = atomicAdd(&g_acc, 0.0);  // re-read: sees all adds
            out[0] = (float)(total / TOTAL_TERMS);
            g_acc = 0.0;
            g_cnt = 0u;
        }
    }
}

extern "C" void kernel_launch(void* const* d_in, const int* in_sizes, int n_in,
                              void* d_out, int out_size)
{
    const float* feat   = (const float*)d_in[0];
    const int*   labels = (const int*)  d_in[1];
    const int*   dirs   = (const int*)  d_in[2];
    float*       out    = (float*)d_out;

    dim3 grid(NBAND, NB, SPLITS);   // (14, 8, 6) = 672 blocks, single wave at 5/SM
    dcl_kernel<<<grid, 256>>>(feat, labels, dirs, out);
}